// round 16
// baseline (speedup 1.0000x reference)
#include <cuda_runtime.h>
#include <cuda_fp16.h>
#include <math.h>

// ---------------- problem constants ----------------
#define Nn    50000
#define Ee    1600000
#define EF    1650000          // E + N self loops
#define SCANB 13               // scan blocks: 13*1024 int4 = 53248 >= 12500
#define HISTB 1563             // hist blocks: ceil((Ee/4)/256)

// output layout (float32, flattened in return order)
#define W_OFF  0               // weights [25001]
#define V_OFF  25001           // value   [1]
#define EI_OFF 25002           // edge_index_full [2, EF]
#define A1_OFF (25002 + 2*EF)  // alpha1 [EF, 4]  (8B-aligned only!)

// ---------------- device scratch ----------------
// node record: rec[2n] = ss1 (fp32 x4), rec[2n+1] = x (fp16 x5, packed, padded)
__device__ __align__(16) float4 g_rec [Nn*2];
__device__ __align__(16) float  g_sdd1[Nn*8];    // [sd1(4) | den1(4)] per node
__device__ __align__(16) __half g_h2h [Nn*32];   // layer2 features, fp16 (32 ch)
__device__ float g_ss2[Nn], g_sd2[Nn];
__device__ float g_scores[Nn];
__device__ float g_gsum[32];
__device__ float g_wsum;                         // softmax denominator
__device__ int   g_hctr;                         // head grid-barrier counter
__device__ float g_eap[HISTB + 1];               // easum partials (overwrite-only)
__device__ float g_eamean;
__device__ __align__(16) float g_c1[4];
__device__ float g_c2;
// CSR-by-dst structures (real edges only; self loops handled analytically)
__device__ __align__(16) int g_cnt[Nn];          // zero at start (BSS / self-restored)
__device__ __align__(16) int g_off[Nn + 4];
__device__ __align__(16) unsigned short g_rank[Ee];  // within-segment rank per edge
__device__ __align__(16) unsigned g_sa[Ee];      // [fp16 a | uint16 src] per edge
__device__ int g_bpref[32];                      // mailboxes: 0 = empty, v = prefix+1

// ---------------- helpers ----------------
__device__ __forceinline__ float wredsum(float v) {
#pragma unroll
    for (int o = 16; o; o >>= 1) v += __shfl_xor_sync(0xffffffffu, v, o);
    return v;
}
__device__ __forceinline__ float lrelu(float x) { return x >= 0.f ? x : 0.2f * x; }
__device__ __forceinline__ float elu(float x)   { return x > 0.f ? x : expm1f(x); }
__device__ __forceinline__ int   sa_src(unsigned q) { return (int)(q & 0xFFFFu); }
__device__ __forceinline__ float sa_a(unsigned q) {
    return __half2float(__ushort_as_half((unsigned short)(q >> 16)));
}

// ---------------- kernels ----------------
// consts: c1/c2/eamean only (Ms/Md now computed inside node1 blocks)
__global__ void k_consts(const float* __restrict__ We1, const float* __restrict__ ae1,
                         const float* __restrict__ We2, const float* __restrict__ ae2) {
    __shared__ float esm[4];
    int t = threadIdx.x;            // 128 threads; warp == head
    int lane = t & 31, h = t >> 5;
    float es = 0.f;
    for (int i = t; i < HISTB; i += 128) es += g_eap[i];
    es = wredsum(es);
    if (lane == 0) esm[h] = es;
    float p = We1[t] * ae1[t];
    p = wredsum(p);
    if (lane == 0) g_c1[h] = p;
    if (t < 32) {
        float q = We2[t] * ae2[t];
        q = wredsum(q);
        if (t == 0) g_c2 = q;
    }
    __syncthreads();
    if (t == 0) g_eamean = (esm[0] + esm[1] + esm[2] + esm[3]) * (1.0f / Ee);
}

// emit edge_index_full: 4 edges/thread, int4 loads + float2 stores (8B-aligned dst)
__global__ void k_eif(const int* __restrict__ ei, float* __restrict__ out) {
    int q = blockIdx.x * blockDim.x + threadIdx.x;   // quad index
    int e = q * 4;
    if (e >= EF) return;
    float s0, s1, s2, s3, d0, d1, d2, d3;
    if (e < Ee) {        // Ee divisible by 4: quad never straddles
        int4 sp = ((const int4*)ei)[q];
        int4 dp = *(const int4*)(ei + Ee + e);
        s0 = (float)sp.x; s1 = (float)sp.y; s2 = (float)sp.z; s3 = (float)sp.w;
        d0 = (float)dp.x; d1 = (float)dp.y; d2 = (float)dp.z; d3 = (float)dp.w;
    } else {
        float b = (float)(e - Ee);
        s0 = d0 = b; s1 = d1 = b + 1.f; s2 = d2 = b + 2.f; s3 = d3 = b + 3.f;
    }
    float2* os = (float2*)(out + EI_OFF + e);
    float2* od = (float2*)(out + EI_OFF + EF + e);
    os[0] = make_float2(s0, s1); os[1] = make_float2(s2, s3);
    od[0] = make_float2(d0, d1); od[1] = make_float2(d2, d3);
}

// histogram + rank capture + easum partials: 4 edges/thread.
__global__ void k_hist(const int* __restrict__ ei, const float* __restrict__ ea) {
    __shared__ float sm[8];
    int q = blockIdx.x * blockDim.x + threadIdx.x;   // quad index
    int lane = threadIdx.x & 31, w = threadIdx.x >> 5;
    float es = 0.f;
    if (q * 4 < Ee) {
        int4 d = *(const int4*)(ei + Ee + q * 4);
        ushort4 r;
        r.x = (unsigned short)atomicAdd(&g_cnt[d.x], 1);
        r.y = (unsigned short)atomicAdd(&g_cnt[d.y], 1);
        r.z = (unsigned short)atomicAdd(&g_cnt[d.z], 1);
        r.w = (unsigned short)atomicAdd(&g_cnt[d.w], 1);
        ((ushort4*)g_rank)[q] = r;
        float4 a4 = ((const float4*)ea)[q];
        es = (a4.x + a4.y) + (a4.z + a4.w);
    }
    es = wredsum(es);
    if (lane == 0) sm[w] = es;
    __syncthreads();
    if (threadIdx.x == 0) {
        float b = 0.f;
        for (int j = 0; j < (int)(blockDim.x >> 5); j++) b += sm[j];
        g_eap[blockIdx.x] = b;
    }
}

// decoupled chained scan: self-restoring.
__global__ void __launch_bounds__(1024) k_scan() {
    __shared__ int wsum[32];
    __shared__ int s_pref;
    const int M4 = Nn / 4;                 // 12500
    int b = blockIdx.x, t = threadIdx.x, lane = t & 31, w = t >> 5;
    if (b == 0) {
        if (t < 32) g_gsum[t] = 0.f;
        if (t == 32) g_wsum = 0.f;
        if (t == 33) g_hctr = 0;
    }
    int idx = b * 1024 + t;
    int4 v = (idx < M4) ? ((const int4*)g_cnt)[idx] : make_int4(0, 0, 0, 0);
    if (idx < M4) ((int4*)g_cnt)[idx] = make_int4(0, 0, 0, 0);   // restore for replay
    int tsum = v.x + v.y + v.z + v.w;
    int val = tsum;
#pragma unroll
    for (int o = 1; o < 32; o <<= 1) { int x = __shfl_up_sync(0xffffffffu, val, o); if (lane >= o) val += x; }
    if (lane == 31) wsum[w] = val;
    __syncthreads();
    if (w == 0) {
        int x = wsum[lane];
#pragma unroll
        for (int o = 1; o < 32; o <<= 1) { int y = __shfl_up_sync(0xffffffffu, x, o); if (lane >= o) x += y; }
        wsum[lane] = x;
    }
    __syncthreads();
    int btot = wsum[31];
    int excl = ((w > 0) ? wsum[w - 1] : 0) + val - tsum;   // exclusive within block
    if (t == 0) {
        int pref = 0;
        if (b > 0) {
            int m;
            while ((m = atomicAdd(&g_bpref[b], 0)) == 0) __nanosleep(64);
            pref = m - 1;
            atomicExch(&g_bpref[b], 0);                    // reset mailbox for replay
        }
        atomicExch(&g_bpref[b + 1], pref + btot + 1);
        s_pref = pref;
    }
    __syncthreads();
    int base = s_pref;
    if (idx < M4) {
        int4 o;
        o.x = base + excl; o.y = o.x + v.x; o.z = o.y + v.y; o.w = o.z + v.z;
        ((int4*)g_off)[idx] = o;
        if (idx == M4 - 1) g_off[Nn] = o.w + v.w;
    }
}

// scatter: ATOMIC-FREE. slot = off[dst] + rank. 4 edges/thread.
__global__ void k_scatter(const int* __restrict__ ei, const float* __restrict__ ea) {
    int q = blockIdx.x * blockDim.x + threadIdx.x;
    if (q * 4 >= Ee) return;
    int4 s4 = ((const int4*)ei)[q];
    int4 d4 = *(const int4*)(ei + Ee + q * 4);
    float4 a4 = ((const float4*)ea)[q];
    ushort4 r4 = ((const ushort4*)g_rank)[q];
    unsigned a0 = (unsigned)__half_as_ushort(__float2half_rn(a4.x));
    unsigned a1 = (unsigned)__half_as_ushort(__float2half_rn(a4.y));
    unsigned a2 = (unsigned)__half_as_ushort(__float2half_rn(a4.z));
    unsigned a3 = (unsigned)__half_as_ushort(__float2half_rn(a4.w));
    g_sa[g_off[d4.x] + r4.x] = (unsigned)s4.x | (a0 << 16);
    g_sa[g_off[d4.y] + r4.y] = (unsigned)s4.y | (a1 << 16);
    g_sa[g_off[d4.z] + r4.z] = (unsigned)s4.z | (a2 << 16);
    g_sa[g_off[d4.w] + r4.w] = (unsigned)s4.w | (a3 << 16);
}

// node prep: STANDALONE (computes its own Ms/Md prologue per block; no consts
// dependency). Block = 128 threads. Thread per node afterwards.
__global__ void __launch_bounds__(128) k_node1(
        const float* __restrict__ x, const float* __restrict__ W1,
        const float* __restrict__ as1, const float* __restrict__ ad1) {
    __shared__ float Ms[20], Md[20];
    __shared__ float red[8];
    int t = threadIdx.x, lane = t & 31, h = t >> 5;
    // prologue: Ms[k][h], Md[k][h] = sum_ch W1[k*128+ch]*a{s,d}1[ch] per head
    float asv = as1[t], adv = ad1[t];
#pragma unroll
    for (int k = 0; k < 5; k++) {
        float ms = wredsum(W1[k*128 + t] * asv);
        float md = wredsum(W1[k*128 + t] * adv);
        if (lane == 0) { Ms[k*4 + h] = ms; Md[k*4 + h] = md; }
    }
    __syncthreads();
    (void)red;
    int stride = gridDim.x * blockDim.x;
    for (int n = blockIdx.x * blockDim.x + t; n < Nn; n += stride) {
        float xk[5];
#pragma unroll
        for (int k = 0; k < 5; k++) xk[k] = x[n*5 + k];
        float ss[4] = {0,0,0,0}, sd[4] = {0,0,0,0};
#pragma unroll
        for (int k = 0; k < 5; k++)
#pragma unroll
            for (int hh = 0; hh < 4; hh++) {
                ss[hh] += xk[k] * Ms[k*4 + hh];
                sd[hh] += xk[k] * Md[k*4 + hh];
            }
        g_rec[2*n] = make_float4(ss[0], ss[1], ss[2], ss[3]);
        __half2 p01 = __floats2half2_rn(xk[0], xk[1]);
        __half2 p23 = __floats2half2_rn(xk[2], xk[3]);
        __half2 p4z = __floats2half2_rn(xk[4], 0.f);
        uint4 u;
        u.x = *reinterpret_cast<unsigned*>(&p01);
        u.y = *reinterpret_cast<unsigned*>(&p23);
        u.z = *reinterpret_cast<unsigned*>(&p4z);
        u.w = 0u;
        ((uint4*)g_rec)[2*n + 1] = u;
        ((float4*)g_sdd1)[n*2] = make_float4(sd[0], sd[1], sd[2], sd[3]);
    }
}

// FUSED layer-1 aggregation + layer-2 projection: warp per node.
// 8 lanes per head mainloop; 3-stage butterfly reduce; W2T LDS.128 epilogue.
__global__ void __launch_bounds__(256) k_agg1f(
        const float* __restrict__ W1, const float* __restrict__ W2,
        const float* __restrict__ b1,
        const float* __restrict__ as2, const float* __restrict__ ad2) {
    __shared__ float W1s[640];
    __shared__ float W2T[32][132];
    __shared__ __align__(16) float hs[8][128];
    int t = threadIdx.x, lane = t & 31, w = t >> 5;
    for (int i = t; i < 640; i += 256) W1s[i] = W1[i];
    for (int i = t; i < 4096; i += 256) W2T[i & 31][i >> 5] = W2[i];
    __syncthreads();
    int warp = (blockIdx.x * blockDim.x + t) >> 5;
    int nwarps = (gridDim.x * blockDim.x) >> 5;
    int h = lane >> 3, pl = lane & 7;
    float4 cc4 = *(const float4*)g_c1;
    float chc = (h == 0) ? cc4.x : (h == 1) ? cc4.y : (h == 2) ? cc4.z : cc4.w;
    float eam = g_eamean;
    float4 bb = ((const float4*)b1)[lane];
    float asv = as2[lane], adv = ad2[lane];
    for (int d = warp; d < Nn; d += nwarps) {
        int beg = g_off[d], end = g_off[d+1];
        float sdh = g_sdd1[d*8 + h];
        float den = 0.f;
        float ax[5] = {0.f, 0.f, 0.f, 0.f, 0.f};
        if (pl == 0) {      // self loop: own head only
            float4 ssv = g_rec[2*d];
            float ssh = (h == 0) ? ssv.x : (h == 1) ? ssv.y : (h == 2) ? ssv.z : ssv.w;
            uint4 xp = ((const uint4*)g_rec)[2*d + 1];
            float2 x01 = __half22float2(*(__half2*)&xp.x);
            float2 x23 = __half22float2(*(__half2*)&xp.y);
            float2 x4_ = __half22float2(*(__half2*)&xp.z);
            float n = __expf(lrelu(ssh + sdh + eam*chc));
            den += n;
            ax[0] += n*x01.x; ax[1] += n*x01.y; ax[2] += n*x23.x;
            ax[3] += n*x23.y; ax[4] += n*x4_.x;
        }
        int i = beg + pl;
        for (; i + 8 < end; i += 16) {
            unsigned m0 = g_sa[i], m1 = g_sa[i + 8];
            int s0 = sa_src(m0), s1 = sa_src(m1);
            float4 sv0 = g_rec[2*s0];
            float4 sv1 = g_rec[2*s1];
            uint4 xp0 = ((const uint4*)g_rec)[2*s0 + 1];
            uint4 xp1 = ((const uint4*)g_rec)[2*s1 + 1];
            float sh0 = (h == 0) ? sv0.x : (h == 1) ? sv0.y : (h == 2) ? sv0.z : sv0.w;
            float sh1 = (h == 0) ? sv1.x : (h == 1) ? sv1.y : (h == 2) ? sv1.z : sv1.w;
            float n0 = __expf(lrelu(sh0 + sdh + sa_a(m0)*chc));
            float n1 = __expf(lrelu(sh1 + sdh + sa_a(m1)*chc));
            float2 a01 = __half22float2(*(__half2*)&xp0.x);
            float2 a23 = __half22float2(*(__half2*)&xp0.y);
            float2 a4_ = __half22float2(*(__half2*)&xp0.z);
            float2 b01 = __half22float2(*(__half2*)&xp1.x);
            float2 b23 = __half22float2(*(__half2*)&xp1.y);
            float2 b4_ = __half22float2(*(__half2*)&xp1.z);
            den += n0 + n1;
            ax[0] += n0*a01.x + n1*b01.x;
            ax[1] += n0*a01.y + n1*b01.y;
            ax[2] += n0*a23.x + n1*b23.x;
            ax[3] += n0*a23.y + n1*b23.y;
            ax[4] += n0*a4_.x + n1*b4_.x;
        }
        if (i < end) {
            unsigned m0 = g_sa[i];
            int s0 = sa_src(m0);
            float4 sv0 = g_rec[2*s0];
            uint4 xp0 = ((const uint4*)g_rec)[2*s0 + 1];
            float sh0 = (h == 0) ? sv0.x : (h == 1) ? sv0.y : (h == 2) ? sv0.z : sv0.w;
            float n0 = __expf(lrelu(sh0 + sdh + sa_a(m0)*chc));
            float2 a01 = __half22float2(*(__half2*)&xp0.x);
            float2 a23 = __half22float2(*(__half2*)&xp0.y);
            float2 a4_ = __half22float2(*(__half2*)&xp0.z);
            den += n0;
            ax[0] += n0*a01.x; ax[1] += n0*a01.y; ax[2] += n0*a23.x;
            ax[3] += n0*a23.y; ax[4] += n0*a4_.x;
        }
#pragma unroll
        for (int o = 4; o; o >>= 1) {
            den += __shfl_xor_sync(0xffffffffu, den, o);
#pragma unroll
            for (int k = 0; k < 5; k++) ax[k] += __shfl_xor_sync(0xffffffffu, ax[k], o);
        }
        float d0 = __shfl_sync(0xffffffffu, den, 0);
        float d1 = __shfl_sync(0xffffffffu, den, 8);
        float d2 = __shfl_sync(0xffffffffu, den, 16);
        float d3 = __shfl_sync(0xffffffffu, den, 24);
        if (lane == 0)
            ((float4*)g_sdd1)[d*2 + 1] = make_float4(d0, d1, d2, d3);
        float inv = 1.0f / (den + 1e-16f);
        float hv[4];
#pragma unroll
        for (int j = 0; j < 4; j++) {
            int chn = lane*4 + j;
            float o = ax[0]*W1s[chn] + ax[1]*W1s[128+chn] + ax[2]*W1s[256+chn]
                    + ax[3]*W1s[384+chn] + ax[4]*W1s[512+chn];
            hv[j] = o * inv;
        }
        ((float4*)hs[w])[lane] = make_float4(elu(hv[0] + bb.x), elu(hv[1] + bb.y),
                                             elu(hv[2] + bb.z), elu(hv[3] + bb.w));
        __syncwarp();
        float acc2 = 0.f;
        const float4* hs4 = (const float4*)hs[w];
#pragma unroll 8
        for (int j4 = 0; j4 < 32; j4++) {
            float4 hv4 = hs4[j4];                       // broadcast
            float4 wv = *(const float4*)&W2T[lane][j4*4];
            acc2 += hv4.x*wv.x + hv4.y*wv.y + hv4.z*wv.z + hv4.w*wv.w;
        }
        g_h2h[d*32 + lane] = __float2half_rn(acc2);
        float ps = wredsum(acc2 * asv);
        float pd = wredsum(acc2 * adv);
        if (lane == 0) { g_ss2[d] = ps; g_sd2[d] = pd; }
        __syncwarp();
    }
}

// edge-parallel alpha1 writer: 2 edges/thread, coalesced float2 stores
__global__ void k_alphaE(const int* __restrict__ ei, const float* __restrict__ ea,
                         float* __restrict__ out) {
    int p = blockIdx.x * blockDim.x + threadIdx.x;
    int e = p * 2;
    if (e >= EF) return;
    int s0, d0, s1, d1; float a0, a1;
    if (e < Ee) {        // Ee even: pair never straddles
        int2 sp = ((const int2*)ei)[p];
        int2 dp = *(const int2*)(ei + Ee + e);
        float2 ap = ((const float2*)ea)[p];
        s0 = sp.x; s1 = sp.y; d0 = dp.x; d1 = dp.y; a0 = ap.x; a1 = ap.y;
    } else {
        s0 = d0 = e - Ee; s1 = d1 = e - Ee + 1;
        a0 = a1 = g_eamean;
    }
    float4 cc = *(const float4*)g_c1;
    float4 ssA = g_rec[2*s0];
    float4 sdA = ((const float4*)g_sdd1)[d0*2];
    float4 ddA = ((const float4*)g_sdd1)[d0*2 + 1];
    float4 ssB = g_rec[2*s1];
    float4 sdB = ((const float4*)g_sdd1)[d1*2];
    float4 ddB = ((const float4*)g_sdd1)[d1*2 + 1];
    float2* ao = (float2*)(out + A1_OFF + 4*e);
    ao[0] = make_float2(__expf(lrelu(ssA.x + sdA.x + a0*cc.x)) / (ddA.x + 1e-16f),
                        __expf(lrelu(ssA.y + sdA.y + a0*cc.y)) / (ddA.y + 1e-16f));
    ao[1] = make_float2(__expf(lrelu(ssA.z + sdA.z + a0*cc.z)) / (ddA.z + 1e-16f),
                        __expf(lrelu(ssA.w + sdA.w + a0*cc.w)) / (ddA.w + 1e-16f));
    ao[2] = make_float2(__expf(lrelu(ssB.x + sdB.x + a1*cc.x)) / (ddB.x + 1e-16f),
                        __expf(lrelu(ssB.y + sdB.y + a1*cc.y)) / (ddB.y + 1e-16f));
    ao[3] = make_float2(__expf(lrelu(ssB.z + sdB.z + a1*cc.z)) / (ddB.z + 1e-16f),
                        __expf(lrelu(ssB.w + sdB.w + a1*cc.w)) / (ddB.w + 1e-16f));
}

// layer-2 aggregation + node head: warp per node, 2 edges per warp-pass (half2).
__global__ void __launch_bounds__(256) k_agg2(
        const float* __restrict__ b2, const float* __restrict__ Wa,
        const float* __restrict__ ba) {
    __shared__ float sacc[32];
    int t = threadIdx.x, lane = t & 31;
    int pl = lane & 15, grp = lane >> 4;
    if (t < 32) sacc[t] = 0.f;
    __syncthreads();
    int warp = (blockIdx.x * blockDim.x + t) >> 5;
    int nwarps = (gridDim.x * blockDim.x) >> 5;
    float c = g_c2, eam = g_eamean;
    float2 bl = ((const float2*)b2)[pl];
    float2 wl = ((const float2*)Wa)[pl];
    float bb = ba[0];
    float gacc0 = 0.f, gacc1 = 0.f;
    const __half2* h2p = (const __half2*)g_h2h;
    for (int d = warp; d < Nn; d += nwarps) {
        int beg = g_off[d], end = g_off[d+1];
        int L = end - beg + 1;                 // virtual items incl. self loop
        float sdv = g_sd2[d];
        float acc0 = 0.f, acc1 = 0.f, den = 0.f;
        int j = grp;
        if (grp == 0) {                         // item 0 = self loop
            float n = __expf(lrelu(g_ss2[d] + sdv + eam*c));
            float2 v = __half22float2(h2p[d*16 + pl]);
            den += n; acc0 += n*v.x; acc1 += n*v.y;
            j = 2;
        }
        for (; j + 2 < L; j += 4) {             // two items per group per pass
            unsigned m0 = g_sa[beg + j - 1];
            unsigned m1 = g_sa[beg + j + 1];
            int s0i = sa_src(m0), s1i = sa_src(m1);
            float n0 = __expf(lrelu(g_ss2[s0i] + sdv + sa_a(m0)*c));
            float n1 = __expf(lrelu(g_ss2[s1i] + sdv + sa_a(m1)*c));
            float2 v0 = __half22float2(h2p[s0i*16 + pl]);
            float2 v1 = __half22float2(h2p[s1i*16 + pl]);
            den += n0 + n1;
            acc0 += n0*v0.x + n1*v1.x;
            acc1 += n0*v0.y + n1*v1.y;
        }
        for (; j < L; j += 2) {
            unsigned m0 = g_sa[beg + j - 1];
            int s0i = sa_src(m0);
            float n0 = __expf(lrelu(g_ss2[s0i] + sdv + sa_a(m0)*c));
            float2 v0 = __half22float2(h2p[s0i*16 + pl]);
            den += n0; acc0 += n0*v0.x; acc1 += n0*v0.y;
        }
        acc0 += __shfl_xor_sync(0xffffffffu, acc0, 16);
        acc1 += __shfl_xor_sync(0xffffffffu, acc1, 16);
        den  += __shfl_xor_sync(0xffffffffu, den, 16);
        float inv = 1.0f / (den + 1e-16f);
        float v0 = elu(acc0*inv + bl.x);
        float v1 = elu(acc1*inv + bl.y);
        float p = v0*wl.x + v1*wl.y;
#pragma unroll
        for (int o = 8; o; o >>= 1) p += __shfl_xor_sync(0xffffffffu, p, o);
        if (lane == 0) g_scores[d] = p + bb;
        if (grp == 0) { gacc0 += v0; gacc1 += v1; }
    }
    if (grp == 0) {
        atomicAdd(&sacc[2*pl],   gacc0);
        atomicAdd(&sacc[2*pl+1], gacc1);
    }
    __syncthreads();
    if (t < 32) atomicAdd(&g_gsum[t], sacc[t]);
}

// fused softmax head: single kernel, spin grid barrier (<=148 blocks = 1 wave).
__global__ void k_headF(const float* __restrict__ cash, const int* __restrict__ stock_idx,
                        const float* __restrict__ Wc, const float* __restrict__ bc,
                        int ns, float* __restrict__ out) {
    __shared__ float sm[8];
    __shared__ float sInv;
    int t = threadIdx.x, lane = t & 31, w = t >> 5;
    int i = blockIdx.x * blockDim.x + t;
    float e = 0.f;
    if (i <= ns) {
        float v = (i == 0) ? cash[0] : g_scores[stock_idx[i-1]];
        e = __expf(v);
    }
    float s = wredsum(e);
    if (lane == 0) sm[w] = s;
    __syncthreads();
    if (t == 0) {
        float b = 0.f;
        for (int j = 0; j < (int)(blockDim.x >> 5); j++) b += sm[j];
        atomicAdd(&g_wsum, b);
        __threadfence();
        atomicAdd(&g_hctr, 1);
    }
    if (blockIdx.x == 0 && t < 32) {
        float p = wredsum(g_gsum[t] * (1.0f / Nn) * Wc[t]);
        if (t == 0) out[V_OFF] = p + bc[0];
    }
    if (t == 0) {
        while (atomicAdd(&g_hctr, 0) < (int)gridDim.x) __nanosleep(32);
        sInv = 1.0f / g_wsum;
    }
    __syncthreads();
    if (i <= ns) out[W_OFF + i] = e * sInv;
}

// ---------------- launch ----------------
extern "C" void kernel_launch(void* const* d_in, const int* in_sizes, int n_in,
                              void* d_out, int out_size) {
    const float* x    = (const float*)d_in[0];
    const float* ea   = (const float*)d_in[1];
    const float* W1   = (const float*)d_in[2];
    const float* as1  = (const float*)d_in[3];
    const float* ad1  = (const float*)d_in[4];
    const float* We1  = (const float*)d_in[5];
    const float* ae1  = (const float*)d_in[6];
    const float* b1   = (const float*)d_in[7];
    const float* W2   = (const float*)d_in[8];
    const float* as2  = (const float*)d_in[9];
    const float* ad2  = (const float*)d_in[10];
    const float* We2  = (const float*)d_in[11];
    const float* ae2  = (const float*)d_in[12];
    const float* b2   = (const float*)d_in[13];
    const float* Wa   = (const float*)d_in[14];
    const float* ba   = (const float*)d_in[15];
    const float* cash = (const float*)d_in[16];
    const float* Wc   = (const float*)d_in[17];
    const float* bc   = (const float*)d_in[18];
    const int*   ei   = (const int*)  d_in[19];
    const int*   sidx = (const int*)  d_in[20];
    float* out = (float*)d_out;
    int ns = in_sizes[20];

    // lazy one-time stream/event/occupancy setup (host-side objects only)
    static cudaStream_t sA = nullptr, sB = nullptr;
    static cudaEvent_t evFork, evHist, evNode1, evAgg1, evAlpha, evEnd;
    static int gridA1 = 0, gridA2 = 0;
    if (!sA) {
        cudaStreamCreateWithFlags(&sA, cudaStreamNonBlocking);
        cudaStreamCreateWithFlags(&sB, cudaStreamNonBlocking);
        cudaEventCreateWithFlags(&evFork,  cudaEventDisableTiming);
        cudaEventCreateWithFlags(&evHist,  cudaEventDisableTiming);
        cudaEventCreateWithFlags(&evNode1, cudaEventDisableTiming);
        cudaEventCreateWithFlags(&evAgg1,  cudaEventDisableTiming);
        cudaEventCreateWithFlags(&evAlpha, cudaEventDisableTiming);
        cudaEventCreateWithFlags(&evEnd,   cudaEventDisableTiming);
        int sms = 148, nb = 0;
        cudaDeviceGetAttribute(&sms, cudaDevAttrMultiProcessorCount, 0);
        cudaOccupancyMaxActiveBlocksPerMultiprocessor(&nb, k_agg1f, 256, 0);
        gridA1 = (nb > 0 ? nb : 4) * sms;
        cudaOccupancyMaxActiveBlocksPerMultiprocessor(&nb, k_agg2, 256, 0);
        gridA2 = (nb > 0 ? nb : 8) * sms;
        if (gridA2 > 6250) gridA2 = 6250;   // no more than one warp per node
        if (gridA1 > 6250) gridA1 = 6250;
    }

    // fork from the harness's (captured) stream
    cudaEventRecord(evFork, 0);
    cudaStreamWaitEvent(sA, evFork, 0);
    cudaStreamWaitEvent(sB, evFork, 0);

    // stream A: hist(+easum) -> scan -> scatter -> agg -> head
    k_hist   <<<HISTB, 256, 0, sA>>>(ei, ea);
    cudaEventRecord(evHist, sA);
    k_scan   <<<SCANB, 1024, 0, sA>>>();
    k_scatter<<<(Ee/4 + 255) / 256, 256, 0, sA>>>(ei, ea);

    // stream B: node1 (standalone) -> consts (waits hist partials) -> eif
    k_node1 <<<392, 128, 0, sB>>>(x, W1, as1, ad1);
    cudaStreamWaitEvent(sB, evHist, 0);
    k_consts<<<1, 128, 0, sB>>>(We1, ae1, We2, ae2);
    cudaEventRecord(evNode1, sB);      // node records + consts done
    k_eif   <<<(EF/4 + 255) / 256, 256, 0, sB>>>(ei, out);

    cudaStreamWaitEvent(sA, evNode1, 0);                // records, sd1, consts
    k_agg1f  <<<gridA1, 256, 0, sA>>>(W1, W2, b1, as2, ad2);
    cudaEventRecord(evAgg1, sA);

    // stream B: alpha writer overlaps agg2 (disjoint data)
    cudaStreamWaitEvent(sB, evAgg1, 0);                 // denominators
    k_alphaE<<<(EF/2 + 255) / 256, 256, 0, sB>>>(ei, ea, out);
    cudaEventRecord(evAlpha, sB);

    k_agg2  <<<gridA2, 256, 0, sA>>>(b2, Wa, ba);
    k_headF <<<(ns + 256) / 256, 256, 0, sA>>>(cash, sidx, Wc, bc, ns, out);
    cudaEventRecord(evEnd, sA);

    // join both streams back into the harness stream
    cudaStreamWaitEvent(0, evEnd, 0);
    cudaStreamWaitEvent(0, evAlpha, 0);
}

// round 17
// speedup vs baseline: 1.0615x; 1.0615x over previous
#include <cuda_runtime.h>
#include <cuda_fp16.h>
#include <math.h>

// ---------------- problem constants ----------------
#define Nn    50000
#define Ee    1600000
#define EF    1650000          // E + N self loops
#define SCANB 13               // scan blocks: 13*1024 int4 = 53248 >= 12500

// output layout (float32, flattened in return order)
#define W_OFF  0               // weights [25001]
#define V_OFF  25001           // value   [1]
#define EI_OFF 25002           // edge_index_full [2, EF]
#define A1_OFF (25002 + 2*EF)  // alpha1 [EF, 4]  (8B-aligned only!)

// ---------------- device scratch ----------------
// node record: rec[2n] = ss1 (fp32 x4), rec[2n+1] = x (fp16 x5, packed, padded)
__device__ __align__(16) float4 g_rec [Nn*2];
__device__ __align__(16) float  g_sdd1[Nn*8];    // [sd1(4) | den1(4)] per node
__device__ __align__(16) __half g_h2h [Nn*32];   // layer2 features, fp16 (32 ch)
__device__ float g_ss2[Nn], g_sd2[Nn];
__device__ float g_scores[Nn];
__device__ float g_gsum[32];
__device__ float g_wsum;                         // softmax denominator
__device__ int   g_hctr;                         // head grid-barrier counter
__device__ float g_eap[512];                     // easum partials (overwrite-only)
__device__ float g_eamean;
__device__ __align__(16) float g_c1[4];
__device__ float g_c2;
__device__ float g_Ms[20], g_Md[20];             // (5 x 4) score matrices: x @ M = s
// CSR-by-dst structures (real edges only; self loops handled analytically)
__device__ __align__(16) int g_cnt[Nn];          // zero at start (BSS / self-restored)
__device__ __align__(16) int g_off[Nn + 4];
__device__ __align__(16) unsigned short g_rank[Ee];  // within-segment rank per edge
__device__ __align__(16) unsigned g_sa[Ee];      // [fp16 a | uint16 src] per edge
__device__ int g_bpref[32];                      // mailboxes: 0 = empty, v = prefix+1

// ---------------- helpers ----------------
__device__ __forceinline__ float wredsum(float v) {
#pragma unroll
    for (int o = 16; o; o >>= 1) v += __shfl_xor_sync(0xffffffffu, v, o);
    return v;
}
__device__ __forceinline__ float lrelu(float x) { return x >= 0.f ? x : 0.2f * x; }
__device__ __forceinline__ float elu(float x)   { return x > 0.f ? x : expm1f(x); }
__device__ __forceinline__ int   sa_src(unsigned q) { return (int)(q & 0xFFFFu); }
__device__ __forceinline__ float sa_a(unsigned q) {
    return __half2float(__ushort_as_half((unsigned short)(q >> 16)));
}

// ---------------- kernels ----------------
// easum partials: overwrite-only, no pre-zeroing needed
__global__ void k_easum(const float* __restrict__ ea) {
    float s = 0.f;
    for (int i = blockIdx.x * blockDim.x + threadIdx.x; i < Ee; i += gridDim.x * blockDim.x)
        s += ea[i];
    s = wredsum(s);
    __shared__ float sm[8];
    int lane = threadIdx.x & 31, w = threadIdx.x >> 5;
    if (lane == 0) sm[w] = s;
    __syncthreads();
    if (threadIdx.x == 0) {
        float b = 0.f;
        for (int i = 0; i < (int)(blockDim.x >> 5); i++) b += sm[i];
        g_eap[blockIdx.x] = b;
    }
}

// consts: c1/c2/eamean (from partials) + score matrices Ms/Md (5x4)
__global__ void k_consts(const float* __restrict__ W1,
                         const float* __restrict__ as1, const float* __restrict__ ad1,
                         const float* __restrict__ We1, const float* __restrict__ ae1,
                         const float* __restrict__ We2, const float* __restrict__ ae2) {
    __shared__ float esm[4];
    int t = threadIdx.x;            // 128 threads; warp == head
    int lane = t & 31, h = t >> 5;
    float es = 0.f;
    for (int i = t; i < 512; i += 128) es += g_eap[i];
    es = wredsum(es);
    if (lane == 0) esm[h] = es;
    float p = We1[t] * ae1[t];
    p = wredsum(p);
    if (lane == 0) g_c1[h] = p;
    float asv = as1[t], adv = ad1[t];
#pragma unroll
    for (int k = 0; k < 5; k++) {
        float ms = wredsum(W1[k*128 + t] * asv);
        float md = wredsum(W1[k*128 + t] * adv);
        if (lane == 0) { g_Ms[k*4 + h] = ms; g_Md[k*4 + h] = md; }
    }
    if (t < 32) {
        float q = We2[t] * ae2[t];
        q = wredsum(q);
        if (t == 0) g_c2 = q;
    }
    __syncthreads();
    if (t == 0) g_eamean = (esm[0] + esm[1] + esm[2] + esm[3]) * (1.0f / Ee);
}

// emit edge_index_full: 4 edges/thread, int4 loads + float2 stores (8B-aligned dst)
__global__ void k_eif(const int* __restrict__ ei, float* __restrict__ out) {
    int q = blockIdx.x * blockDim.x + threadIdx.x;   // quad index
    int e = q * 4;
    if (e >= EF) return;
    float s0, s1, s2, s3, d0, d1, d2, d3;
    if (e < Ee) {        // Ee divisible by 4: quad never straddles
        int4 sp = ((const int4*)ei)[q];
        int4 dp = *(const int4*)(ei + Ee + e);
        s0 = (float)sp.x; s1 = (float)sp.y; s2 = (float)sp.z; s3 = (float)sp.w;
        d0 = (float)dp.x; d1 = (float)dp.y; d2 = (float)dp.z; d3 = (float)dp.w;
    } else {
        float b = (float)(e - Ee);
        s0 = d0 = b; s1 = d1 = b + 1.f; s2 = d2 = b + 2.f; s3 = d3 = b + 3.f;
    }
    float2* os = (float2*)(out + EI_OFF + e);
    float2* od = (float2*)(out + EI_OFF + EF + e);
    os[0] = make_float2(s0, s1); os[1] = make_float2(s2, s3);
    od[0] = make_float2(d0, d1); od[1] = make_float2(d2, d3);
}

// histogram + rank capture: 4 edges/thread.
__global__ void k_hist(const int* __restrict__ ei) {
    int q = blockIdx.x * blockDim.x + threadIdx.x;   // quad index
    if (q * 4 >= Ee) return;
    int4 d = *(const int4*)(ei + Ee + q * 4);
    ushort4 r;
    r.x = (unsigned short)atomicAdd(&g_cnt[d.x], 1);
    r.y = (unsigned short)atomicAdd(&g_cnt[d.y], 1);
    r.z = (unsigned short)atomicAdd(&g_cnt[d.z], 1);
    r.w = (unsigned short)atomicAdd(&g_cnt[d.w], 1);
    ((ushort4*)g_rank)[q] = r;
}

// decoupled chained scan: self-restoring.
__global__ void __launch_bounds__(1024) k_scan() {
    __shared__ int wsum[32];
    __shared__ int s_pref;
    const int M4 = Nn / 4;                 // 12500
    int b = blockIdx.x, t = threadIdx.x, lane = t & 31, w = t >> 5;
    if (b == 0) {
        if (t < 32) g_gsum[t] = 0.f;
        if (t == 32) g_wsum = 0.f;
        if (t == 33) g_hctr = 0;
    }
    int idx = b * 1024 + t;
    int4 v = (idx < M4) ? ((const int4*)g_cnt)[idx] : make_int4(0, 0, 0, 0);
    if (idx < M4) ((int4*)g_cnt)[idx] = make_int4(0, 0, 0, 0);   // restore for replay
    int tsum = v.x + v.y + v.z + v.w;
    int val = tsum;
#pragma unroll
    for (int o = 1; o < 32; o <<= 1) { int x = __shfl_up_sync(0xffffffffu, val, o); if (lane >= o) val += x; }
    if (lane == 31) wsum[w] = val;
    __syncthreads();
    if (w == 0) {
        int x = wsum[lane];
#pragma unroll
        for (int o = 1; o < 32; o <<= 1) { int y = __shfl_up_sync(0xffffffffu, x, o); if (lane >= o) x += y; }
        wsum[lane] = x;
    }
    __syncthreads();
    int btot = wsum[31];
    int excl = ((w > 0) ? wsum[w - 1] : 0) + val - tsum;   // exclusive within block
    if (t == 0) {
        int pref = 0;
        if (b > 0) {
            int m;
            while ((m = atomicAdd(&g_bpref[b], 0)) == 0) __nanosleep(64);
            pref = m - 1;
            atomicExch(&g_bpref[b], 0);                    // reset mailbox for replay
        }
        atomicExch(&g_bpref[b + 1], pref + btot + 1);
        s_pref = pref;
    }
    __syncthreads();
    int base = s_pref;
    if (idx < M4) {
        int4 o;
        o.x = base + excl; o.y = o.x + v.x; o.z = o.y + v.y; o.w = o.z + v.z;
        ((int4*)g_off)[idx] = o;
        if (idx == M4 - 1) g_off[Nn] = o.w + v.w;
    }
}

// scatter: ATOMIC-FREE. slot = off[dst] + rank. 4 edges/thread.
__global__ void k_scatter(const int* __restrict__ ei, const float* __restrict__ ea) {
    int q = blockIdx.x * blockDim.x + threadIdx.x;
    if (q * 4 >= Ee) return;
    int4 s4 = ((const int4*)ei)[q];
    int4 d4 = *(const int4*)(ei + Ee + q * 4);
    float4 a4 = ((const float4*)ea)[q];
    ushort4 r4 = ((const ushort4*)g_rank)[q];
    unsigned a0 = (unsigned)__half_as_ushort(__float2half_rn(a4.x));
    unsigned a1 = (unsigned)__half_as_ushort(__float2half_rn(a4.y));
    unsigned a2 = (unsigned)__half_as_ushort(__float2half_rn(a4.z));
    unsigned a3 = (unsigned)__half_as_ushort(__float2half_rn(a4.w));
    g_sa[g_off[d4.x] + r4.x] = (unsigned)s4.x | (a0 << 16);
    g_sa[g_off[d4.y] + r4.y] = (unsigned)s4.y | (a1 << 16);
    g_sa[g_off[d4.z] + r4.z] = (unsigned)s4.z | (a2 << 16);
    g_sa[g_off[d4.w] + r4.w] = (unsigned)s4.w | (a3 << 16);
}

// node prep: thread per node. ss1/sd1 = x @ Ms/Md (5x4). Packed node record.
__global__ void k_node1(const float* __restrict__ x) {
    __shared__ float Ms[20], Md[20];
    int t = threadIdx.x;
    if (t < 20) { Ms[t] = g_Ms[t]; Md[t] = g_Md[t]; }
    __syncthreads();
    int stride = gridDim.x * blockDim.x;
    for (int n = blockIdx.x * blockDim.x + t; n < Nn; n += stride) {
        float xk[5];
#pragma unroll
        for (int k = 0; k < 5; k++) xk[k] = x[n*5 + k];
        float ss[4] = {0,0,0,0}, sd[4] = {0,0,0,0};
#pragma unroll
        for (int k = 0; k < 5; k++)
#pragma unroll
            for (int h = 0; h < 4; h++) {
                ss[h] += xk[k] * Ms[k*4 + h];
                sd[h] += xk[k] * Md[k*4 + h];
            }
        g_rec[2*n] = make_float4(ss[0], ss[1], ss[2], ss[3]);
        __half2 p01 = __floats2half2_rn(xk[0], xk[1]);
        __half2 p23 = __floats2half2_rn(xk[2], xk[3]);
        __half2 p4z = __floats2half2_rn(xk[4], 0.f);
        uint4 u;
        u.x = *reinterpret_cast<unsigned*>(&p01);
        u.y = *reinterpret_cast<unsigned*>(&p23);
        u.z = *reinterpret_cast<unsigned*>(&p4z);
        u.w = 0u;
        ((uint4*)g_rec)[2*n + 1] = u;
        ((float4*)g_sdd1)[n*2] = make_float4(sd[0], sd[1], sd[2], sd[3]);
    }
}

// FUSED layer-1 aggregation + layer-2 projection: warp per node.
// 8 lanes per head mainloop; 3-stage butterfly reduce; W2T LDS.128 epilogue.
__global__ void __launch_bounds__(256) k_agg1f(
        const float* __restrict__ W1, const float* __restrict__ W2,
        const float* __restrict__ b1,
        const float* __restrict__ as2, const float* __restrict__ ad2) {
    __shared__ float W1s[640];
    __shared__ float W2T[32][132];
    __shared__ __align__(16) float hs[8][128];
    int t = threadIdx.x, lane = t & 31, w = t >> 5;
    for (int i = t; i < 640; i += 256) W1s[i] = W1[i];
    for (int i = t; i < 4096; i += 256) W2T[i & 31][i >> 5] = W2[i];
    __syncthreads();
    int warp = (blockIdx.x * blockDim.x + t) >> 5;
    int nwarps = (gridDim.x * blockDim.x) >> 5;
    int h = lane >> 3, pl = lane & 7;
    float4 cc4 = *(const float4*)g_c1;
    float chc = (h == 0) ? cc4.x : (h == 1) ? cc4.y : (h == 2) ? cc4.z : cc4.w;
    float eam = g_eamean;
    float4 bb = ((const float4*)b1)[lane];
    float asv = as2[lane], adv = ad2[lane];
    for (int d = warp; d < Nn; d += nwarps) {
        int beg = g_off[d], end = g_off[d+1];
        float sdh = g_sdd1[d*8 + h];
        float den = 0.f;
        float ax[5] = {0.f, 0.f, 0.f, 0.f, 0.f};
        if (pl == 0) {      // self loop: own head only
            float4 ssv = g_rec[2*d];
            float ssh = (h == 0) ? ssv.x : (h == 1) ? ssv.y : (h == 2) ? ssv.z : ssv.w;
            uint4 xp = ((const uint4*)g_rec)[2*d + 1];
            float2 x01 = __half22float2(*(__half2*)&xp.x);
            float2 x23 = __half22float2(*(__half2*)&xp.y);
            float2 x4_ = __half22float2(*(__half2*)&xp.z);
            float n = __expf(lrelu(ssh + sdh + eam*chc));
            den += n;
            ax[0] += n*x01.x; ax[1] += n*x01.y; ax[2] += n*x23.x;
            ax[3] += n*x23.y; ax[4] += n*x4_.x;
        }
        int i = beg + pl;
        for (; i + 8 < end; i += 16) {
            unsigned m0 = g_sa[i], m1 = g_sa[i + 8];
            int s0 = sa_src(m0), s1 = sa_src(m1);
            float4 sv0 = g_rec[2*s0];
            float4 sv1 = g_rec[2*s1];
            uint4 xp0 = ((const uint4*)g_rec)[2*s0 + 1];
            uint4 xp1 = ((const uint4*)g_rec)[2*s1 + 1];
            float sh0 = (h == 0) ? sv0.x : (h == 1) ? sv0.y : (h == 2) ? sv0.z : sv0.w;
            float sh1 = (h == 0) ? sv1.x : (h == 1) ? sv1.y : (h == 2) ? sv1.z : sv1.w;
            float n0 = __expf(lrelu(sh0 + sdh + sa_a(m0)*chc));
            float n1 = __expf(lrelu(sh1 + sdh + sa_a(m1)*chc));
            float2 a01 = __half22float2(*(__half2*)&xp0.x);
            float2 a23 = __half22float2(*(__half2*)&xp0.y);
            float2 a4_ = __half22float2(*(__half2*)&xp0.z);
            float2 b01 = __half22float2(*(__half2*)&xp1.x);
            float2 b23 = __half22float2(*(__half2*)&xp1.y);
            float2 b4_ = __half22float2(*(__half2*)&xp1.z);
            den += n0 + n1;
            ax[0] += n0*a01.x + n1*b01.x;
            ax[1] += n0*a01.y + n1*b01.y;
            ax[2] += n0*a23.x + n1*b23.x;
            ax[3] += n0*a23.y + n1*b23.y;
            ax[4] += n0*a4_.x + n1*b4_.x;
        }
        if (i < end) {
            unsigned m0 = g_sa[i];
            int s0 = sa_src(m0);
            float4 sv0 = g_rec[2*s0];
            uint4 xp0 = ((const uint4*)g_rec)[2*s0 + 1];
            float sh0 = (h == 0) ? sv0.x : (h == 1) ? sv0.y : (h == 2) ? sv0.z : sv0.w;
            float n0 = __expf(lrelu(sh0 + sdh + sa_a(m0)*chc));
            float2 a01 = __half22float2(*(__half2*)&xp0.x);
            float2 a23 = __half22float2(*(__half2*)&xp0.y);
            float2 a4_ = __half22float2(*(__half2*)&xp0.z);
            den += n0;
            ax[0] += n0*a01.x; ax[1] += n0*a01.y; ax[2] += n0*a23.x;
            ax[3] += n0*a23.y; ax[4] += n0*a4_.x;
        }
#pragma unroll
        for (int o = 4; o; o >>= 1) {
            den += __shfl_xor_sync(0xffffffffu, den, o);
#pragma unroll
            for (int k = 0; k < 5; k++) ax[k] += __shfl_xor_sync(0xffffffffu, ax[k], o);
        }
        float d0 = __shfl_sync(0xffffffffu, den, 0);
        float d1 = __shfl_sync(0xffffffffu, den, 8);
        float d2 = __shfl_sync(0xffffffffu, den, 16);
        float d3 = __shfl_sync(0xffffffffu, den, 24);
        if (lane == 0)
            ((float4*)g_sdd1)[d*2 + 1] = make_float4(d0, d1, d2, d3);
        float inv = 1.0f / (den + 1e-16f);
        float hv[4];
#pragma unroll
        for (int j = 0; j < 4; j++) {
            int chn = lane*4 + j;
            float o = ax[0]*W1s[chn] + ax[1]*W1s[128+chn] + ax[2]*W1s[256+chn]
                    + ax[3]*W1s[384+chn] + ax[4]*W1s[512+chn];
            hv[j] = o * inv;
        }
        ((float4*)hs[w])[lane] = make_float4(elu(hv[0] + bb.x), elu(hv[1] + bb.y),
                                             elu(hv[2] + bb.z), elu(hv[3] + bb.w));
        __syncwarp();
        float acc2 = 0.f;
        const float4* hs4 = (const float4*)hs[w];
#pragma unroll 8
        for (int j4 = 0; j4 < 32; j4++) {
            float4 hv4 = hs4[j4];                       // broadcast
            float4 wv = *(const float4*)&W2T[lane][j4*4];
            acc2 += hv4.x*wv.x + hv4.y*wv.y + hv4.z*wv.z + hv4.w*wv.w;
        }
        g_h2h[d*32 + lane] = __float2half_rn(acc2);
        float ps = wredsum(acc2 * asv);
        float pd = wredsum(acc2 * adv);
        if (lane == 0) { g_ss2[d] = ps; g_sd2[d] = pd; }
        __syncwarp();
    }
}

// edge-parallel alpha1 writer: 2 edges/thread, coalesced float2 stores
__global__ void k_alphaE(const int* __restrict__ ei, const float* __restrict__ ea,
                         float* __restrict__ out) {
    int p = blockIdx.x * blockDim.x + threadIdx.x;
    int e = p * 2;
    if (e >= EF) return;
    int s0, d0, s1, d1; float a0, a1;
    if (e < Ee) {        // Ee even: pair never straddles
        int2 sp = ((const int2*)ei)[p];
        int2 dp = *(const int2*)(ei + Ee + e);
        float2 ap = ((const float2*)ea)[p];
        s0 = sp.x; s1 = sp.y; d0 = dp.x; d1 = dp.y; a0 = ap.x; a1 = ap.y;
    } else {
        s0 = d0 = e - Ee; s1 = d1 = e - Ee + 1;
        a0 = a1 = g_eamean;
    }
    float4 cc = *(const float4*)g_c1;
    float4 ssA = g_rec[2*s0];
    float4 sdA = ((const float4*)g_sdd1)[d0*2];
    float4 ddA = ((const float4*)g_sdd1)[d0*2 + 1];
    float4 ssB = g_rec[2*s1];
    float4 sdB = ((const float4*)g_sdd1)[d1*2];
    float4 ddB = ((const float4*)g_sdd1)[d1*2 + 1];
    float2* ao = (float2*)(out + A1_OFF + 4*e);
    ao[0] = make_float2(__expf(lrelu(ssA.x + sdA.x + a0*cc.x)) / (ddA.x + 1e-16f),
                        __expf(lrelu(ssA.y + sdA.y + a0*cc.y)) / (ddA.y + 1e-16f));
    ao[1] = make_float2(__expf(lrelu(ssA.z + sdA.z + a0*cc.z)) / (ddA.z + 1e-16f),
                        __expf(lrelu(ssA.w + sdA.w + a0*cc.w)) / (ddA.w + 1e-16f));
    ao[2] = make_float2(__expf(lrelu(ssB.x + sdB.x + a1*cc.x)) / (ddB.x + 1e-16f),
                        __expf(lrelu(ssB.y + sdB.y + a1*cc.y)) / (ddB.y + 1e-16f));
    ao[3] = make_float2(__expf(lrelu(ssB.z + sdB.z + a1*cc.z)) / (ddB.z + 1e-16f),
                        __expf(lrelu(ssB.w + sdB.w + a1*cc.w)) / (ddB.w + 1e-16f));
}

// layer-2 aggregation + node head: warp per node, 2 edges per warp-pass (half2).
__global__ void __launch_bounds__(256) k_agg2(
        const float* __restrict__ b2, const float* __restrict__ Wa,
        const float* __restrict__ ba) {
    __shared__ float sacc[32];
    int t = threadIdx.x, lane = t & 31;
    int pl = lane & 15, grp = lane >> 4;
    if (t < 32) sacc[t] = 0.f;
    __syncthreads();
    int warp = (blockIdx.x * blockDim.x + t) >> 5;
    int nwarps = (gridDim.x * blockDim.x) >> 5;
    float c = g_c2, eam = g_eamean;
    float2 bl = ((const float2*)b2)[pl];
    float2 wl = ((const float2*)Wa)[pl];
    float bb = ba[0];
    float gacc0 = 0.f, gacc1 = 0.f;
    const __half2* h2p = (const __half2*)g_h2h;
    for (int d = warp; d < Nn; d += nwarps) {
        int beg = g_off[d], end = g_off[d+1];
        int L = end - beg + 1;                 // virtual items incl. self loop
        float sdv = g_sd2[d];
        float acc0 = 0.f, acc1 = 0.f, den = 0.f;
        int j = grp;
        if (grp == 0) {                         // item 0 = self loop
            float n = __expf(lrelu(g_ss2[d] + sdv + eam*c));
            float2 v = __half22float2(h2p[d*16 + pl]);
            den += n; acc0 += n*v.x; acc1 += n*v.y;
            j = 2;
        }
        for (; j + 2 < L; j += 4) {             // two items per group per pass
            unsigned m0 = g_sa[beg + j - 1];
            unsigned m1 = g_sa[beg + j + 1];
            int s0i = sa_src(m0), s1i = sa_src(m1);
            float n0 = __expf(lrelu(g_ss2[s0i] + sdv + sa_a(m0)*c));
            float n1 = __expf(lrelu(g_ss2[s1i] + sdv + sa_a(m1)*c));
            float2 v0 = __half22float2(h2p[s0i*16 + pl]);
            float2 v1 = __half22float2(h2p[s1i*16 + pl]);
            den += n0 + n1;
            acc0 += n0*v0.x + n1*v1.x;
            acc1 += n0*v0.y + n1*v1.y;
        }
        for (; j < L; j += 2) {
            unsigned m0 = g_sa[beg + j - 1];
            int s0i = sa_src(m0);
            float n0 = __expf(lrelu(g_ss2[s0i] + sdv + sa_a(m0)*c));
            float2 v0 = __half22float2(h2p[s0i*16 + pl]);
            den += n0; acc0 += n0*v0.x; acc1 += n0*v0.y;
        }
        acc0 += __shfl_xor_sync(0xffffffffu, acc0, 16);
        acc1 += __shfl_xor_sync(0xffffffffu, acc1, 16);
        den  += __shfl_xor_sync(0xffffffffu, den, 16);
        float inv = 1.0f / (den + 1e-16f);
        float v0 = elu(acc0*inv + bl.x);
        float v1 = elu(acc1*inv + bl.y);
        float p = v0*wl.x + v1*wl.y;
#pragma unroll
        for (int o = 8; o; o >>= 1) p += __shfl_xor_sync(0xffffffffu, p, o);
        if (lane == 0) g_scores[d] = p + bb;
        if (grp == 0) { gacc0 += v0; gacc1 += v1; }
    }
    if (grp == 0) {
        atomicAdd(&sacc[2*pl],   gacc0);
        atomicAdd(&sacc[2*pl+1], gacc1);
    }
    __syncthreads();
    if (t < 32) atomicAdd(&g_gsum[t], sacc[t]);
}

// fused softmax head: single kernel, spin grid barrier (<=148 blocks = 1 wave).
__global__ void k_headF(const float* __restrict__ cash, const int* __restrict__ stock_idx,
                        const float* __restrict__ Wc, const float* __restrict__ bc,
                        int ns, float* __restrict__ out) {
    __shared__ float sm[8];
    __shared__ float sInv;
    int t = threadIdx.x, lane = t & 31, w = t >> 5;
    int i = blockIdx.x * blockDim.x + t;
    float e = 0.f;
    if (i <= ns) {
        float v = (i == 0) ? cash[0] : g_scores[stock_idx[i-1]];
        e = __expf(v);
    }
    float s = wredsum(e);
    if (lane == 0) sm[w] = s;
    __syncthreads();
    if (t == 0) {
        float b = 0.f;
        for (int j = 0; j < (int)(blockDim.x >> 5); j++) b += sm[j];
        atomicAdd(&g_wsum, b);
        __threadfence();
        atomicAdd(&g_hctr, 1);
    }
    if (blockIdx.x == 0 && t < 32) {
        float p = wredsum(g_gsum[t] * (1.0f / Nn) * Wc[t]);
        if (t == 0) out[V_OFF] = p + bc[0];
    }
    if (t == 0) {
        while (atomicAdd(&g_hctr, 0) < (int)gridDim.x) __nanosleep(32);
        sInv = 1.0f / g_wsum;
    }
    __syncthreads();
    if (i <= ns) out[W_OFF + i] = e * sInv;
}

// ---------------- launch ----------------
extern "C" void kernel_launch(void* const* d_in, const int* in_sizes, int n_in,
                              void* d_out, int out_size) {
    const float* x    = (const float*)d_in[0];
    const float* ea   = (const float*)d_in[1];
    const float* W1   = (const float*)d_in[2];
    const float* as1  = (const float*)d_in[3];
    const float* ad1  = (const float*)d_in[4];
    const float* We1  = (const float*)d_in[5];
    const float* ae1  = (const float*)d_in[6];
    const float* b1   = (const float*)d_in[7];
    const float* W2   = (const float*)d_in[8];
    const float* as2  = (const float*)d_in[9];
    const float* ad2  = (const float*)d_in[10];
    const float* We2  = (const float*)d_in[11];
    const float* ae2  = (const float*)d_in[12];
    const float* b2   = (const float*)d_in[13];
    const float* Wa   = (const float*)d_in[14];
    const float* ba   = (const float*)d_in[15];
    const float* cash = (const float*)d_in[16];
    const float* Wc   = (const float*)d_in[17];
    const float* bc   = (const float*)d_in[18];
    const int*   ei   = (const int*)  d_in[19];
    const int*   sidx = (const int*)  d_in[20];
    float* out = (float*)d_out;
    int ns = in_sizes[20];

    // lazy one-time stream/event/occupancy setup (host-side objects only)
    static cudaStream_t sA = nullptr, sB = nullptr;
    static cudaEvent_t evFork, evNode1, evAgg1, evAlpha, evEnd;
    static int gridA1 = 0, gridA2 = 0;
    if (!sA) {
        cudaStreamCreateWithFlags(&sA, cudaStreamNonBlocking);
        cudaStreamCreateWithFlags(&sB, cudaStreamNonBlocking);
        cudaEventCreateWithFlags(&evFork,  cudaEventDisableTiming);
        cudaEventCreateWithFlags(&evNode1, cudaEventDisableTiming);
        cudaEventCreateWithFlags(&evAgg1,  cudaEventDisableTiming);
        cudaEventCreateWithFlags(&evAlpha, cudaEventDisableTiming);
        cudaEventCreateWithFlags(&evEnd,   cudaEventDisableTiming);
        int sms = 148, nb = 0;
        cudaDeviceGetAttribute(&sms, cudaDevAttrMultiProcessorCount, 0);
        cudaOccupancyMaxActiveBlocksPerMultiprocessor(&nb, k_agg1f, 256, 0);
        gridA1 = (nb > 0 ? nb : 4) * sms;
        cudaOccupancyMaxActiveBlocksPerMultiprocessor(&nb, k_agg2, 256, 0);
        gridA2 = (nb > 0 ? nb : 8) * sms;
        if (gridA2 > 6250) gridA2 = 6250;   // no more than one warp per node
        if (gridA1 > 6250) gridA1 = 6250;
    }

    // fork from the harness's (captured) stream
    cudaEventRecord(evFork, 0);
    cudaStreamWaitEvent(sA, evFork, 0);
    cudaStreamWaitEvent(sB, evFork, 0);

    // stream B: easum -> consts (+M matrices) -> node1 -> edge_index_full
    k_easum <<<512, 256, 0, sB>>>(ea);
    k_consts<<<1, 128, 0, sB>>>(W1, as1, ad1, We1, ae1, We2, ae2);
    k_node1 <<<196, 256, 0, sB>>>(x);
    cudaEventRecord(evNode1, sB);      // implies consts done too
    k_eif   <<<(EF/4 + 255) / 256, 256, 0, sB>>>(ei, out);

    // stream A: CSR build (rank-based, atomic-free scatter) -> agg -> head
    k_hist   <<<(Ee/4 + 255) / 256, 256, 0, sA>>>(ei);
    k_scan   <<<SCANB, 1024, 0, sA>>>();
    k_scatter<<<(Ee/4 + 255) / 256, 256, 0, sA>>>(ei, ea);
    cudaStreamWaitEvent(sA, evNode1, 0);                // records, sd1, consts
    k_agg1f  <<<gridA1, 256, 0, sA>>>(W1, W2, b1, as2, ad2);
    cudaEventRecord(evAgg1, sA);

    // stream B: alpha writer overlaps agg2 (disjoint data)
    cudaStreamWaitEvent(sB, evAgg1, 0);                 // denominators
    k_alphaE<<<(EF/2 + 255) / 256, 256, 0, sB>>>(ei, ea, out);
    cudaEventRecord(evAlpha, sB);

    k_agg2  <<<gridA2, 256, 0, sA>>>(b2, Wa, ba);
    k_headF <<<(ns + 256) / 256, 256, 0, sA>>>(cash, sidx, Wc, bc, ns, out);
    cudaEventRecord(evEnd, sA);

    // join both streams back into the harness stream
    cudaStreamWaitEvent(0, evEnd, 0);
    cudaStreamWaitEvent(0, evAlpha, 0);
}